// round 14
// baseline (speedup 1.0000x reference)
#include <cuda_runtime.h>

#define NSTATE 64
#define NPAIR  (NSTATE / 2)

__device__ __forceinline__ float rcpa(float x) {
    float r; asm("rcp.approx.f32 %0,%1;" : "=f"(r) : "f"(x)); return r;
}

// Pairwise-fused Cauchy kernel + lane-split over states.
//   wa/(g-la) + wb/(g-lb) = (beta*g + alpha) / (g^2 - s*g + p),  g = i*x:
//   D = (p_r + s_i*x - x^2) + i*(p_i - s_r*x)
//   N = (a_r - b_i*x)       + i*(a_i + b_r*x)
// Lane l and lane l^16 each evaluate 16 of the 32 pairs for BOTH lanes' k
// values; a shfl_xor(16) merge recombines the full sums.
// smem: pair j and pair j+16 interleaved 80B apart -> the two broadcast
// address groups per LDS.128 hit disjoint banks (0..3 vs 20..23 mod 32).
__global__ __launch_bounds__(256, 3) void s4_cauchy_kernel(
    const float* __restrict__ Lr, const float* __restrict__ Li,
    const float* __restrict__ Pr, const float* __restrict__ Pi,
    const float* __restrict__ Qr, const float* __restrict__ Qi,
    const float* __restrict__ Br, const float* __restrict__ Bi,
    const float* __restrict__ Cr, const float* __restrict__ Ci,
    const float* __restrict__ step_ptr,
    float* __restrict__ out, int L)
{
    __shared__ __align__(16) float4 sPK[16][2][5];  // [j][half][D,N00,N01,N10,N11]
    __shared__ float sStep;

    const int t = threadIdx.x;
    if (t == 0) sStep = step_ptr[0];
    if (t < NPAIR) {
        const int a = 2 * t, b = 2 * t + 1;
        float lar = Lr[a], lai = Li[a], lbr = Lr[b], lbi = Li[b];

        float w[2][4][2];
        for (int sidx = 0; sidx < 2; sidx++) {
            int n = (sidx == 0) ? a : b;
            float cr = Cr[n], ci = Ci[n];
            float qr = Qr[n], qi = Qi[n];
            float br = Br[n], bi = Bi[n];
            float pr = Pr[n], pi = Pi[n];
            w[sidx][0][0] = cr * br + ci * bi;  w[sidx][0][1] = cr * bi - ci * br; // conjC*B
            w[sidx][1][0] = cr * pr + ci * pi;  w[sidx][1][1] = cr * pi - ci * pr; // conjC*P
            w[sidx][2][0] = qr * br + qi * bi;  w[sidx][2][1] = qr * bi - qi * br; // conjQ*B
            w[sidx][3][0] = qr * pr + qi * pi;  w[sidx][3][1] = qr * pi - qi * pr; // conjQ*P
        }

        float s_r = lar + lbr, s_i = lai + lbi;
        float p_r = lar * lbr - lai * lbi;
        float p_i = lar * lbi + lai * lbr;

        const int j = t & 15, h = t >> 4;
        sPK[j][h][0] = make_float4(p_r, s_i, p_i, -s_r);
        for (int ij = 0; ij < 4; ij++) {
            float war = w[0][ij][0], wai = w[0][ij][1];
            float wbr = w[1][ij][0], wbi = w[1][ij][1];
            float b_r = war + wbr, b_i = wai + wbi;
            float a_r = -(war * lbr - wai * lbi + wbr * lar - wbi * lai);
            float a_i = -(war * lbi + wai * lbr + wbr * lai + wbi * lar);
            sPK[j][h][1 + ij] = make_float4(a_r, -b_i, a_i, b_r);
        }
    }
    __syncthreads();

    const int lane = t & 31;
    const int half = lane >> 4;          // which 16-pair slice this lane owns
    const int k = blockIdx.x * 256 + t;

    // x = (2/step)*tan(pi*k/L); partner's x via shfl (saves a sincosf)
    const float PI = 3.14159265358979323846f;
    float sn, cs;
    sincosf(PI * ((float)k / (float)L), &sn, &cs);
    float u   = __fdividef(sn, cs);
    float xs  = (2.0f / sStep) * u;
    float xo  = __shfl_xor_sync(0xffffffffu, xs, 16);
    float x2s = xs * xs, x2o = xo * xo;

    float accS[8], accO[8];
#pragma unroll
    for (int q = 0; q < 8; q++) { accS[q] = 0.f; accO[q] = 0.f; }

#define BODY(X, X2, ACC)                                                      \
    do {                                                                      \
        float dr = fmaf(d.y, (X), d.x) - (X2);                                \
        float di = fmaf(d.w, (X), d.z);                                       \
        float m  = fmaf(dr, dr, di * di);                                     \
        float r  = rcpa(m);                                                   \
        float zr = dr * r;                                                    \
        float t2 = di * r;                                                    \
        float nr = fmaf(n0.y, (X), n0.x), ni = fmaf(n0.w, (X), n0.z);         \
        ACC[0] = fmaf(nr, zr, fmaf(ni,  t2, ACC[0]));                         \
        ACC[1] = fmaf(ni, zr, fmaf(nr, -t2, ACC[1]));                         \
        nr = fmaf(n1.y, (X), n1.x); ni = fmaf(n1.w, (X), n1.z);               \
        ACC[2] = fmaf(nr, zr, fmaf(ni,  t2, ACC[2]));                         \
        ACC[3] = fmaf(ni, zr, fmaf(nr, -t2, ACC[3]));                         \
        nr = fmaf(n2.y, (X), n2.x); ni = fmaf(n2.w, (X), n2.z);               \
        ACC[4] = fmaf(nr, zr, fmaf(ni,  t2, ACC[4]));                         \
        ACC[5] = fmaf(ni, zr, fmaf(nr, -t2, ACC[5]));                         \
        nr = fmaf(n3.y, (X), n3.x); ni = fmaf(n3.w, (X), n3.z);               \
        ACC[6] = fmaf(nr, zr, fmaf(ni,  t2, ACC[6]));                         \
        ACC[7] = fmaf(ni, zr, fmaf(nr, -t2, ACC[7]));                         \
    } while (0)

#pragma unroll 4
    for (int j = 0; j < 16; j++) {
        float4 d  = sPK[j][half][0];
        float4 n0 = sPK[j][half][1];
        float4 n1 = sPK[j][half][2];
        float4 n2 = sPK[j][half][3];
        float4 n3 = sPK[j][half][4];
        BODY(xs, x2s, accS);   // my slice, my k
        BODY(xo, x2o, accO);   // my slice, partner's k
    }
#undef BODY

    // Merge: my k's full sum = my slice + partner's slice (partner's accO is
    // the partials it computed for MY k).
    float tot[8];
#pragma unroll
    for (int q = 0; q < 8; q++)
        tot[q] = accS[q] + __shfl_xor_sync(0xffffffffu, accO[q], 16);

    float k00r = tot[0], k00i = tot[1];
    float k01r = tot[2], k01i = tot[3];
    float k10r = tot[4], k10i = tot[5];
    float k11r = tot[6], k11i = tot[7];

    // atRoots = c * (k00 - k01*k10/(1+k11)),  c = 1 + i*u
    float tr = k01r * k10r - k01i * k10i;
    float ti = k01r * k10i + k01i * k10r;
    float er = 1.0f + k11r, ei = k11i;
    float rinv = __fdividef(1.0f, er * er + ei * ei);
    float sr = (tr * er + ti * ei) * rinv;
    float si = (ti * er - tr * ei) * rinv;
    float ar = k00r - sr, ai = k00i - si;

    if (k < L) out[k] = ar - u * ai;   // Re((1+iu)*(ar + i*ai))
}

extern "C" void kernel_launch(void* const* d_in, const int* in_sizes, int n_in,
                              void* d_out, int out_size) {
    const float* Lr = (const float*)d_in[0];
    const float* Li = (const float*)d_in[1];
    const float* Pr = (const float*)d_in[2];
    const float* Pi = (const float*)d_in[3];
    const float* Qr = (const float*)d_in[4];
    const float* Qi = (const float*)d_in[5];
    const float* Br = (const float*)d_in[6];
    const float* Bi = (const float*)d_in[7];
    const float* Cr = (const float*)d_in[8];
    const float* Ci = (const float*)d_in[9];
    const float* step = (const float*)d_in[10];

    int L = out_size;  // L float32 elements = Re(atRoots)

    int threads = 256;
    int blocks = (L + threads - 1) / threads;  // 512 for L=131071
    s4_cauchy_kernel<<<blocks, threads>>>(Lr, Li, Pr, Pi, Qr, Qi, Br, Bi,
                                          Cr, Ci, step, (float*)d_out, L);
}

// round 15
// speedup vs baseline: 1.4717x; 1.4717x over previous
#include <cuda_runtime.h>

#define NSTATE 64
#define NPAIR  (NSTATE / 2)

__device__ __forceinline__ float rcpa(float x) {
    float r; asm("rcp.approx.f32 %0,%1;" : "=f"(r) : "f"(x)); return r;
}

// Pairwise-fused Cauchy kernel.
//   wa/(g-la) + wb/(g-lb) = (beta*g + alpha) / (g^2 - s*g + p)
// with g = i*x purely imaginary:
//   D  = (p_r + s_i*x - x^2) + i*(p_i - s_r*x)
//   N  = (a_r - b_i*x)       + i*(a_i + b_r*x)
// Per pair, packed contiguously (80 B):
//   [0] = {p_r, s_i, p_i, -s_r}
//   [1..4] = {a_r, -b_i, a_i, b_r} for ij = 00, 01, 10, 11
__global__ __launch_bounds__(128, 7) void s4_cauchy_kernel(
    const float* __restrict__ Lr, const float* __restrict__ Li,
    const float* __restrict__ Pr, const float* __restrict__ Pi,
    const float* __restrict__ Qr, const float* __restrict__ Qi,
    const float* __restrict__ Br, const float* __restrict__ Bi,
    const float* __restrict__ Cr, const float* __restrict__ Ci,
    const float* __restrict__ step_ptr,
    float* __restrict__ out, int L)
{
    __shared__ __align__(16) float4 sP[NPAIR][5];
    __shared__ float sStep;

    const int t = threadIdx.x;
    if (t == 0) sStep = step_ptr[0];
    if (t < NPAIR) {
        const int a = 2 * t, b = 2 * t + 1;
        float lar = Lr[a], lai = Li[a], lbr = Lr[b], lbi = Li[b];

        // per-state numerators w_ij = a_i * b_j  (a0=conj C, a1=conj Q; b0=B, b1=P)
        float w[2][4][2];
        for (int sidx = 0; sidx < 2; sidx++) {
            int n = (sidx == 0) ? a : b;
            float cr = Cr[n], ci = Ci[n];
            float qr = Qr[n], qi = Qi[n];
            float br = Br[n], bi = Bi[n];
            float pr = Pr[n], pi = Pi[n];
            w[sidx][0][0] = cr * br + ci * bi;  w[sidx][0][1] = cr * bi - ci * br; // conjC*B
            w[sidx][1][0] = cr * pr + ci * pi;  w[sidx][1][1] = cr * pi - ci * pr; // conjC*P
            w[sidx][2][0] = qr * br + qi * bi;  w[sidx][2][1] = qr * bi - qi * br; // conjQ*B
            w[sidx][3][0] = qr * pr + qi * pi;  w[sidx][3][1] = qr * pi - qi * pr; // conjQ*P
        }

        // s = la + lb, p = la*lb
        float s_r = lar + lbr, s_i = lai + lbi;
        float p_r = lar * lbr - lai * lbi;
        float p_i = lar * lbi + lai * lbr;
        sP[t][0] = make_float4(p_r, s_i, p_i, -s_r);

        for (int ij = 0; ij < 4; ij++) {
            float war = w[0][ij][0], wai = w[0][ij][1];
            float wbr = w[1][ij][0], wbi = w[1][ij][1];
            // beta = wa + wb ; alpha = -(wa*lb + wb*la)
            float b_r = war + wbr, b_i = wai + wbi;
            float a_r = -(war * lbr - wai * lbi + wbr * lar - wbi * lai);
            float a_i = -(war * lbi + wai * lbr + wbr * lai + wbi * lar);
            sP[t][1 + ij] = make_float4(a_r, -b_i, a_i, b_r);
        }
    }
    __syncthreads();

    const int k = blockIdx.x * 128 + t;

    // x = gi = (2/step)*tan(pi*k/L);  c = 1 + i*u, u = tan(pi*k/L)
    const float PI = 3.14159265358979323846f;
    float sn, cs;
    sincosf(PI * ((float)k / (float)L), &sn, &cs);
    float u  = __fdividef(sn, cs);
    float x  = (2.0f / sStep) * u;
    float x2 = x * x;

    float k00r = 0.f, k00i = 0.f, k01r = 0.f, k01i = 0.f;
    float k10r = 0.f, k10i = 0.f, k11r = 0.f, k11i = 0.f;

#pragma unroll
    for (int n = 0; n < NPAIR; n++) {
        float4 d = sP[n][0];
        float dr = fmaf(d.y, x, d.x) - x2;   // p_r + s_i*x - x^2
        float di = fmaf(d.w, x, d.z);        // p_i - s_r*x
        float m  = fmaf(dr, dr, di * di);
        float r  = rcpa(m);
        float zr = dr * r;                   // 1/D = (dr - i*di) * r
        float t2 = di * r;

        float4 n0 = sP[n][1];
        float nr = fmaf(n0.y, x, n0.x);
        float ni = fmaf(n0.w, x, n0.z);
        k00r = fmaf(nr, zr, fmaf(ni,  t2, k00r));
        k00i = fmaf(ni, zr, fmaf(nr, -t2, k00i));

        float4 n1 = sP[n][2];
        nr = fmaf(n1.y, x, n1.x);
        ni = fmaf(n1.w, x, n1.z);
        k01r = fmaf(nr, zr, fmaf(ni,  t2, k01r));
        k01i = fmaf(ni, zr, fmaf(nr, -t2, k01i));

        float4 n2 = sP[n][3];
        nr = fmaf(n2.y, x, n2.x);
        ni = fmaf(n2.w, x, n2.z);
        k10r = fmaf(nr, zr, fmaf(ni,  t2, k10r));
        k10i = fmaf(ni, zr, fmaf(nr, -t2, k10i));

        float4 n3 = sP[n][4];
        nr = fmaf(n3.y, x, n3.x);
        ni = fmaf(n3.w, x, n3.z);
        k11r = fmaf(nr, zr, fmaf(ni,  t2, k11r));
        k11i = fmaf(ni, zr, fmaf(nr, -t2, k11i));
    }

    // atRoots = c * (k00 - k01*k10/(1+k11)),  c = 1 + i*u
    float tr = k01r * k10r - k01i * k10i;
    float ti = k01r * k10i + k01i * k10r;
    float er = 1.0f + k11r, ei = k11i;
    float rinv = __fdividef(1.0f, er * er + ei * ei);
    float sr = (tr * er + ti * ei) * rinv;
    float si = (ti * er - tr * ei) * rinv;
    float ar = k00r - sr, ai = k00i - si;

    if (k < L) out[k] = ar - u * ai;   // Re((1+iu)*(ar + i*ai))
}

extern "C" void kernel_launch(void* const* d_in, const int* in_sizes, int n_in,
                              void* d_out, int out_size) {
    const float* Lr = (const float*)d_in[0];
    const float* Li = (const float*)d_in[1];
    const float* Pr = (const float*)d_in[2];
    const float* Pi = (const float*)d_in[3];
    const float* Qr = (const float*)d_in[4];
    const float* Qi = (const float*)d_in[5];
    const float* Br = (const float*)d_in[6];
    const float* Bi = (const float*)d_in[7];
    const float* Cr = (const float*)d_in[8];
    const float* Ci = (const float*)d_in[9];
    const float* step = (const float*)d_in[10];

    int L = out_size;  // L float32 elements = Re(atRoots)

    int threads = 128;
    int blocks = (L + threads - 1) / threads;  // 1024 for L=131071
    s4_cauchy_kernel<<<blocks, threads>>>(Lr, Li, Pr, Pi, Qr, Qi, Br, Bi,
                                          Cr, Ci, step, (float*)d_out, L);
}

// round 16
// speedup vs baseline: 1.4975x; 1.0175x over previous
#include <cuda_runtime.h>

#define NSTATE 64
#define NPAIR  (NSTATE / 2)

__device__ __forceinline__ float rcpa(float x) {
    float r; asm("rcp.approx.f32 %0,%1;" : "=f"(r) : "f"(x)); return r;
}

// Pairwise-fused Cauchy kernel, 2 threads per frequency.
//   wa/(g-la) + wb/(g-lb) = (beta*g + alpha) / (g^2 - s*g + p),  g = i*x:
//   D = (p_r + s_i*x - x^2) + i*(p_i - s_r*x)
//   N = (a_r - b_i*x)       + i*(a_i + b_r*x)
// Lanes l and l^16 share one k: each evaluates 16 of the 32 pairs with the
// SAME 8-accumulator structure as the proven R12 loop; one shfl_xor(16)
// merge recombines full sums. Threads = 2*L -> ~48 warps/SM resident.
__global__ __launch_bounds__(128, 12) void s4_cauchy_kernel(
    const float* __restrict__ Lr, const float* __restrict__ Li,
    const float* __restrict__ Pr, const float* __restrict__ Pi,
    const float* __restrict__ Qr, const float* __restrict__ Qi,
    const float* __restrict__ Br, const float* __restrict__ Bi,
    const float* __restrict__ Cr, const float* __restrict__ Ci,
    const float* __restrict__ step_ptr,
    float* __restrict__ out, int L)
{
    __shared__ __align__(16) float4 sP[NPAIR][5];
    __shared__ float sStep;

    const int t = threadIdx.x;
    if (t == 0) sStep = step_ptr[0];
    if (t < NPAIR) {
        const int a = 2 * t, b = 2 * t + 1;
        float lar = Lr[a], lai = Li[a], lbr = Lr[b], lbi = Li[b];

        // per-state numerators w_ij = a_i * b_j (a0=conjC, a1=conjQ; b0=B, b1=P)
        float w[2][4][2];
        for (int sidx = 0; sidx < 2; sidx++) {
            int n = (sidx == 0) ? a : b;
            float cr = Cr[n], ci = Ci[n];
            float qr = Qr[n], qi = Qi[n];
            float br = Br[n], bi = Bi[n];
            float pr = Pr[n], pi = Pi[n];
            w[sidx][0][0] = cr * br + ci * bi;  w[sidx][0][1] = cr * bi - ci * br;
            w[sidx][1][0] = cr * pr + ci * pi;  w[sidx][1][1] = cr * pi - ci * pr;
            w[sidx][2][0] = qr * br + qi * bi;  w[sidx][2][1] = qr * bi - qi * br;
            w[sidx][3][0] = qr * pr + qi * pi;  w[sidx][3][1] = qr * pi - qi * pr;
        }

        float s_r = lar + lbr, s_i = lai + lbi;
        float p_r = lar * lbr - lai * lbi;
        float p_i = lar * lbi + lai * lbr;
        sP[t][0] = make_float4(p_r, s_i, p_i, -s_r);

        for (int ij = 0; ij < 4; ij++) {
            float war = w[0][ij][0], wai = w[0][ij][1];
            float wbr = w[1][ij][0], wbi = w[1][ij][1];
            float b_r = war + wbr, b_i = wai + wbi;
            float a_r = -(war * lbr - wai * lbi + wbr * lar - wbi * lai);
            float a_i = -(war * lbi + wai * lbr + wbr * lai + wbi * lar);
            sP[t][1 + ij] = make_float4(a_r, -b_i, a_i, b_r);
        }
    }
    __syncthreads();

    const int lane = t & 31;
    const int sub  = lane & 15;   // k index within this warp's 16-k tile
    const int half = lane >> 4;   // which 16-pair slice this lane owns
    const int warp = t >> 5;
    const int k = blockIdx.x * 64 + warp * 16 + sub;

    // x = (2/step)*tan(pi*k/L);  c = 1 + i*u, u = tan(pi*k/L)
    const float PI = 3.14159265358979323846f;
    float sn, cs;
    sincosf(PI * ((float)k / (float)L), &sn, &cs);
    float u  = __fdividef(sn, cs);
    float x  = (2.0f / sStep) * u;
    float x2 = x * x;

    float k00r = 0.f, k00i = 0.f, k01r = 0.f, k01i = 0.f;
    float k10r = 0.f, k10i = 0.f, k11r = 0.f, k11i = 0.f;

    const int base = half * 16;
#pragma unroll 8
    for (int nn = 0; nn < 16; nn++) {
        const int n = base + nn;
        float4 d = sP[n][0];
        float dr = fmaf(d.y, x, d.x) - x2;   // p_r + s_i*x - x^2
        float di = fmaf(d.w, x, d.z);        // p_i - s_r*x
        float m  = fmaf(dr, dr, di * di);
        float r  = rcpa(m);
        float zr = dr * r;                   // 1/D = (dr - i*di) * r
        float t2 = di * r;

        float4 n0 = sP[n][1];
        float nr = fmaf(n0.y, x, n0.x);
        float ni = fmaf(n0.w, x, n0.z);
        k00r = fmaf(nr, zr, fmaf(ni,  t2, k00r));
        k00i = fmaf(ni, zr, fmaf(nr, -t2, k00i));

        float4 n1 = sP[n][2];
        nr = fmaf(n1.y, x, n1.x);
        ni = fmaf(n1.w, x, n1.z);
        k01r = fmaf(nr, zr, fmaf(ni,  t2, k01r));
        k01i = fmaf(ni, zr, fmaf(nr, -t2, k01i));

        float4 n2 = sP[n][3];
        nr = fmaf(n2.y, x, n2.x);
        ni = fmaf(n2.w, x, n2.z);
        k10r = fmaf(nr, zr, fmaf(ni,  t2, k10r));
        k10i = fmaf(ni, zr, fmaf(nr, -t2, k10i));

        float4 n3 = sP[n][4];
        nr = fmaf(n3.y, x, n3.x);
        ni = fmaf(n3.w, x, n3.z);
        k11r = fmaf(nr, zr, fmaf(ni,  t2, k11r));
        k11i = fmaf(ni, zr, fmaf(nr, -t2, k11i));
    }

    // Merge the two 16-pair half-sums (lanes l and l^16 hold the same k).
    k00r += __shfl_xor_sync(0xffffffffu, k00r, 16);
    k00i += __shfl_xor_sync(0xffffffffu, k00i, 16);
    k01r += __shfl_xor_sync(0xffffffffu, k01r, 16);
    k01i += __shfl_xor_sync(0xffffffffu, k01i, 16);
    k10r += __shfl_xor_sync(0xffffffffu, k10r, 16);
    k10i += __shfl_xor_sync(0xffffffffu, k10i, 16);
    k11r += __shfl_xor_sync(0xffffffffu, k11r, 16);
    k11i += __shfl_xor_sync(0xffffffffu, k11i, 16);

    // atRoots = c * (k00 - k01*k10/(1+k11)),  c = 1 + i*u
    float tr = k01r * k10r - k01i * k10i;
    float ti = k01r * k10i + k01i * k10r;
    float er = 1.0f + k11r, ei = k11i;
    float rinv = __fdividef(1.0f, er * er + ei * ei);
    float sr = (tr * er + ti * ei) * rinv;
    float si = (ti * er - tr * ei) * rinv;
    float ar = k00r - sr, ai = k00i - si;

    if (half == 0 && k < L) out[k] = ar - u * ai;  // Re((1+iu)*(ar+i*ai))
}

extern "C" void kernel_launch(void* const* d_in, const int* in_sizes, int n_in,
                              void* d_out, int out_size) {
    const float* Lr = (const float*)d_in[0];
    const float* Li = (const float*)d_in[1];
    const float* Pr = (const float*)d_in[2];
    const float* Pi = (const float*)d_in[3];
    const float* Qr = (const float*)d_in[4];
    const float* Qi = (const float*)d_in[5];
    const float* Br = (const float*)d_in[6];
    const float* Bi = (const float*)d_in[7];
    const float* Cr = (const float*)d_in[8];
    const float* Ci = (const float*)d_in[9];
    const float* step = (const float*)d_in[10];

    int L = out_size;  // L float32 elements = Re(atRoots)

    // 64 frequencies per 128-thread block (2 threads per k).
    int threads = 128;
    int blocks = (L + 63) / 64;  // 2048 for L=131071
    s4_cauchy_kernel<<<blocks, threads>>>(Lr, Li, Pr, Pi, Qr, Qi, Br, Bi,
                                          Cr, Ci, step, (float*)d_out, L);
}

// round 17
// speedup vs baseline: 1.5013x; 1.0025x over previous
#include <cuda_runtime.h>

#define NSTATE 64
#define NPAIR  (NSTATE / 2)

__device__ __forceinline__ float rcpa(float x) {
    float r; asm("rcp.approx.f32 %0,%1;" : "=f"(r) : "f"(x)); return r;
}

// Pairwise-fused Cauchy kernel.
//   wa/(g-la) + wb/(g-lb) = (beta*g + alpha) / (g^2 - s*g + p)
// with g = i*x purely imaginary:
//   D  = (p_r + s_i*x - x^2) + i*(p_i - s_r*x)
//   N  = (a_r - b_i*x)       + i*(a_i + b_r*x)
// Per pair, packed contiguously (80 B):
//   [0] = {p_r, s_i, p_i, -s_r}
//   [1..4] = {a_r, -b_i, a_i, b_r} for ij = 00, 01, 10, 11
__global__ __launch_bounds__(128, 7) void s4_cauchy_kernel(
    const float* __restrict__ Lr, const float* __restrict__ Li,
    const float* __restrict__ Pr, const float* __restrict__ Pi,
    const float* __restrict__ Qr, const float* __restrict__ Qi,
    const float* __restrict__ Br, const float* __restrict__ Bi,
    const float* __restrict__ Cr, const float* __restrict__ Ci,
    const float* __restrict__ step_ptr,
    float* __restrict__ out, int L)
{
    __shared__ __align__(16) float4 sP[NPAIR][5];
    __shared__ float sStep;

    const int t = threadIdx.x;
    if (t == 0) sStep = step_ptr[0];
    if (t < NPAIR) {
        const int a = 2 * t, b = 2 * t + 1;
        float lar = Lr[a], lai = Li[a], lbr = Lr[b], lbi = Li[b];

        // per-state numerators w_ij = a_i * b_j (a0=conjC, a1=conjQ; b0=B, b1=P)
        float w[2][4][2];
        for (int sidx = 0; sidx < 2; sidx++) {
            int n = (sidx == 0) ? a : b;
            float cr = Cr[n], ci = Ci[n];
            float qr = Qr[n], qi = Qi[n];
            float br = Br[n], bi = Bi[n];
            float pr = Pr[n], pi = Pi[n];
            w[sidx][0][0] = cr * br + ci * bi;  w[sidx][0][1] = cr * bi - ci * br;
            w[sidx][1][0] = cr * pr + ci * pi;  w[sidx][1][1] = cr * pi - ci * pr;
            w[sidx][2][0] = qr * br + qi * bi;  w[sidx][2][1] = qr * bi - qi * br;
            w[sidx][3][0] = qr * pr + qi * pi;  w[sidx][3][1] = qr * pi - qi * pr;
        }

        // s = la + lb, p = la*lb
        float s_r = lar + lbr, s_i = lai + lbi;
        float p_r = lar * lbr - lai * lbi;
        float p_i = lar * lbi + lai * lbr;
        sP[t][0] = make_float4(p_r, s_i, p_i, -s_r);

        for (int ij = 0; ij < 4; ij++) {
            float war = w[0][ij][0], wai = w[0][ij][1];
            float wbr = w[1][ij][0], wbi = w[1][ij][1];
            // beta = wa + wb ; alpha = -(wa*lb + wb*la)
            float b_r = war + wbr, b_i = wai + wbi;
            float a_r = -(war * lbr - wai * lbi + wbr * lar - wbi * lai);
            float a_i = -(war * lbi + wai * lbr + wbr * lai + wbi * lar);
            sP[t][1 + ij] = make_float4(a_r, -b_i, a_i, b_r);
        }
    }
    __syncthreads();

    const int k = blockIdx.x * 128 + t;

    // x = (2/step)*tan(pi*k/L);  c = 1 + i*u, u = tan(pi*k/L)
    // Fast trig is safe: near the pole (k ~ L/2) the output is dominated by
    // u*ai with ai ~ 1/x, so trig error cancels at leading order.
    const float PI = 3.14159265358979323846f;
    float piOverL = __fdividef(PI, (float)L);
    float ang = (float)k * piOverL;
    float sn, cs;
    __sincosf(ang, &sn, &cs);
    float u  = __fdividef(sn, cs);
    float x  = (2.0f / sStep) * u;
    float x2 = x * x;

    float k00r = 0.f, k00i = 0.f, k01r = 0.f, k01i = 0.f;
    float k10r = 0.f, k10i = 0.f, k11r = 0.f, k11i = 0.f;

#pragma unroll
    for (int n = 0; n < NPAIR; n++) {
        float4 d = sP[n][0];
        float dr = fmaf(d.y, x, d.x) - x2;   // p_r + s_i*x - x^2
        float di = fmaf(d.w, x, d.z);        // p_i - s_r*x
        float m  = fmaf(dr, dr, di * di);
        float r  = rcpa(m);
        float zr = dr * r;                   // 1/D = (dr - i*di) * r
        float t2 = di * r;

        float4 n0 = sP[n][1];
        float nr = fmaf(n0.y, x, n0.x);
        float ni = fmaf(n0.w, x, n0.z);
        k00r = fmaf(nr, zr, fmaf(ni,  t2, k00r));
        k00i = fmaf(ni, zr, fmaf(nr, -t2, k00i));

        float4 n1 = sP[n][2];
        nr = fmaf(n1.y, x, n1.x);
        ni = fmaf(n1.w, x, n1.z);
        k01r = fmaf(nr, zr, fmaf(ni,  t2, k01r));
        k01i = fmaf(ni, zr, fmaf(nr, -t2, k01i));

        float4 n2 = sP[n][3];
        nr = fmaf(n2.y, x, n2.x);
        ni = fmaf(n2.w, x, n2.z);
        k10r = fmaf(nr, zr, fmaf(ni,  t2, k10r));
        k10i = fmaf(ni, zr, fmaf(nr, -t2, k10i));

        float4 n3 = sP[n][4];
        nr = fmaf(n3.y, x, n3.x);
        ni = fmaf(n3.w, x, n3.z);
        k11r = fmaf(nr, zr, fmaf(ni,  t2, k11r));
        k11i = fmaf(ni, zr, fmaf(nr, -t2, k11i));
    }

    // atRoots = c * (k00 - k01*k10/(1+k11)),  c = 1 + i*u
    float tr = k01r * k10r - k01i * k10i;
    float ti = k01r * k10i + k01i * k10r;
    float er = 1.0f + k11r, ei = k11i;
    float rinv = rcpa(fmaf(er, er, ei * ei));
    float sr = (tr * er + ti * ei) * rinv;
    float si = (ti * er - tr * ei) * rinv;
    float ar = k00r - sr, ai = k00i - si;

    if (k < L) out[k] = ar - u * ai;   // Re((1+iu)*(ar + i*ai))
}

extern "C" void kernel_launch(void* const* d_in, const int* in_sizes, int n_in,
                              void* d_out, int out_size) {
    const float* Lr = (const float*)d_in[0];
    const float* Li = (const float*)d_in[1];
    const float* Pr = (const float*)d_in[2];
    const float* Pi = (const float*)d_in[3];
    const float* Qr = (const float*)d_in[4];
    const float* Qi = (const float*)d_in[5];
    const float* Br = (const float*)d_in[6];
    const float* Bi = (const float*)d_in[7];
    const float* Cr = (const float*)d_in[8];
    const float* Ci = (const float*)d_in[9];
    const float* step = (const float*)d_in[10];

    int L = out_size;  // L float32 elements = Re(atRoots)

    int threads = 128;
    int blocks = (L + threads - 1) / threads;  // 1024 for L=131071
    s4_cauchy_kernel<<<blocks, threads>>>(Lr, Li, Pr, Pi, Qr, Qi, Br, Bi,
                                          Cr, Ci, step, (float*)d_out, L);
}